// round 2
// baseline (speedup 1.0000x reference)
#include <cuda_runtime.h>

#define IMW 1024
#define IMH 1024
#define HW  (IMW * IMH)
#define TILE_W 16
#define TILE_H 32
#define HALO_W (TILE_W + 6)   // 22
#define HALO_H (TILE_H + 6)   // 38
#define SSTRIDE 24            // padded row stride (floats)
#define CH_STRIDE (HALO_H * SSTRIDE)
#define EPSR 1e-4f

typedef unsigned long long ull;

// ---- packed f32x2 helpers -------------------------------------------------
__device__ __forceinline__ ull pk2(float lo, float hi) {
    ull r;
    asm("mov.b64 %0, {%1, %2};" : "=l"(r) : "f"(lo), "f"(hi));
    return r;
}
__device__ __forceinline__ void ffma2(ull& d, ull a, ull b) {
    asm("fma.rn.f32x2 %0, %1, %2, %0;" : "+l"(d) : "l"(a), "l"(b));
}
__device__ __forceinline__ ull ffma2g(ull a, ull b, ull c) {
    ull r;
    asm("fma.rn.f32x2 %0, %1, %2, %3;" : "=l"(r) : "l"(a), "l"(b), "l"(c));
    return r;
}
__device__ __forceinline__ ull mul2(ull a, ull b) {
    ull r;
    asm("mul.rn.f32x2 %0, %1, %2;" : "=l"(r) : "l"(a), "l"(b));
    return r;
}
__device__ __forceinline__ ull add2(ull a, ull b) {
    ull r;
    asm("add.rn.f32x2 %0, %1, %2;" : "=l"(r) : "l"(a), "l"(b));
    return r;
}
__device__ __forceinline__ void upk2(ull v, float& lo, float& hi) {
    asm("mov.b64 {%0, %1}, %2;" : "=f"(lo), "=f"(hi) : "l"(v));
}
__device__ __forceinline__ float frcp(float x) {
    float r;
    asm("rcp.approx.f32 %0, %1;" : "=f"(r) : "f"(x));
    return r;
}

// upper-triangle index for 8x8 symmetric (i<=j)
__host__ __device__ constexpr int IDX(int i, int j) {
    return i * 8 - i * (i - 1) / 2 + (j - i);
}

// load one tap: 11 channels, vertical pixel pair packed
__device__ __forceinline__ void loadtap(ull v[11], const float* __restrict__ p) {
#pragma unroll
    for (int ch = 0; ch < 11; ++ch)
        v[ch] = pk2(p[ch * CH_STRIDE], p[ch * CH_STRIDE + SSTRIDE]);
}

// 60 packed accumulations for one tap
__device__ __forceinline__ void fma60(const ull v[11], ull ata[36], ull aty[24]) {
    int k = 0;
#pragma unroll
    for (int i = 0; i < 8; ++i)
#pragma unroll
        for (int j = i; j < 8; ++j) { ffma2(ata[k], v[i], v[j]); ++k; }
#pragma unroll
    for (int i = 0; i < 8; ++i)
#pragma unroll
        for (int c = 0; c < 3; ++c) ffma2(aty[i * 3 + c], v[i], v[8 + c]);
}

__global__ __launch_bounds__(256)
void ls_kernel(const float* __restrict__ inp,
               const float* __restrict__ depth,
               const float* __restrict__ alb,
               const float* __restrict__ nrm,
               float* __restrict__ out)
{
    // 11 channels: [valid(=1), depth, albedo x3, normal x3, input x3]
    __shared__ float S[11 * CH_STRIDE];

    const int tid = threadIdx.x;
    const int bx = blockIdx.x, by = blockIdx.y;
    const int gx0 = bx * TILE_W - 3;
    const int gy0 = by * TILE_H - 3;

    // ---- stage halo tile into smem (zeros outside the image) ----
    for (int idx = tid; idx < HALO_H * HALO_W; idx += 256) {
        const int r = idx / HALO_W;
        const int c = idx - r * HALO_W;
        const int gy = gy0 + r;
        const int gx = gx0 + c;
        float v[11];
        if ((unsigned)gy < (unsigned)IMH && (unsigned)gx < (unsigned)IMW) {
            const int g = gy * IMW + gx;
            v[0] = 1.0f;
            v[1] = depth[g];
            v[2] = alb[g];  v[3] = alb[g + HW];  v[4] = alb[g + 2 * HW];
            v[5] = nrm[g];  v[6] = nrm[g + HW];  v[7] = nrm[g + 2 * HW];
            v[8] = inp[g];  v[9] = inp[g + HW];  v[10] = inp[g + 2 * HW];
        } else {
#pragma unroll
            for (int ch = 0; ch < 11; ++ch) v[ch] = 0.0f;
        }
#pragma unroll
        for (int ch = 0; ch < 11; ++ch)
            S[ch * CH_STRIDE + r * SSTRIDE + c] = v[ch];
    }
    __syncthreads();

    // ---- two vertically adjacent pixels per thread, packed f32x2 ----
    const int lx = tid & 15;
    const int ly0 = (tid >> 4) * 2;

    ull ata[36];  // packed upper triangle of AtA
    ull aty[24];  // packed AtY, i*3+c
#pragma unroll
    for (int i = 0; i < 36; ++i) ata[i] = 0ULL;
#pragma unroll
    for (int i = 0; i < 24; ++i) aty[i] = 0ULL;

    const float* base = &S[ly0 * SSTRIDE + lx];

    // software-pipelined 49-tap loop: prefetch next tap under current FMAs
    ull va[11], vb[11];
    loadtap(va, base);
#pragma unroll 1
    for (int dy = 0; dy < 7; ++dy) {
        const float* rp = base + dy * SSTRIDE;
        loadtap(vb, rp + 1); fma60(va, ata, aty);   // t0
        loadtap(va, rp + 2); fma60(vb, ata, aty);   // t1
        loadtap(vb, rp + 3); fma60(va, ata, aty);   // t2
        loadtap(va, rp + 4); fma60(vb, ata, aty);   // t3
        loadtap(vb, rp + 5); fma60(va, ata, aty);   // t4
        loadtap(va, rp + 6); fma60(vb, ata, aty);   // t5
        if (dy < 6) loadtap(vb, rp + SSTRIDE);
        fma60(va, ata, aty);                        // t6
        // rotate: next row's t0 sits in vb -> move to va
#pragma unroll
        for (int ch = 0; ch < 11; ++ch) va[ch] = vb[ch];
    }

    // ---- packed symmetric solve (both pixels at once) ----
    // AtA += eps*I
    const ull EPS2 = pk2(EPSR, EPSR);
#pragma unroll
    for (int i = 0; i < 8; ++i) ata[IDX(i, i)] = add2(ata[IDX(i, i)], EPS2);

    // RHS = center-pixel features (packed over the two pixels)
    ull rhs[8];
    {
        const float* cp = &S[(ly0 + 3) * SSTRIDE + (lx + 3)];
#pragma unroll
        for (int i = 0; i < 8; ++i)
            rhs[i] = pk2(cp[i * CH_STRIDE], cp[i * CH_STRIDE + SSTRIDE]);
    }

    // symmetric Gaussian elimination on upper triangle (no pivoting: SPD+Tikhonov)
#pragma unroll
    for (int k = 0; k < 8; ++k) {
        float dlo, dhi;
        upk2(ata[IDX(k, k)], dlo, dhi);
        const ull ninv = pk2(-frcp(dlo), -frcp(dhi));
#pragma unroll
        for (int i = k + 1; i < 8; ++i) {
            const ull li = mul2(ata[IDX(k, i)], ninv);   // -a_ki / d_k
            rhs[i] = ffma2g(li, rhs[k], rhs[i]);
#pragma unroll
            for (int j = i; j < 8; ++j)
                ata[IDX(i, j)] = ffma2g(li, ata[IDX(k, j)], ata[IDX(i, j)]);
        }
    }
    // back-substitution (nx = -x)
    ull nx[8];
#pragma unroll
    for (int i = 7; i >= 0; --i) {
        ull s = rhs[i];
#pragma unroll
        for (int j = 7; j > i; --j)
            s = ffma2g(ata[IDX(i, j)], nx[j], s);
        float dlo, dhi;
        upk2(ata[IDX(i, i)], dlo, dhi);
        nx[i] = mul2(s, pk2(-frcp(dlo), -frcp(dhi)));
    }

    // outputs: out_c = x . AtY_c  (= -(nx . AtY_c))
    const int gy = by * TILE_H + ly0;
    const int gx = bx * TILE_W + lx;
#pragma unroll
    for (int c = 0; c < 3; ++c) {
        ull acc = 0ULL;
#pragma unroll
        for (int i = 0; i < 8; ++i)
            ffma2(acc, nx[i], aty[i * 3 + c]);
        float olo, ohi;
        upk2(acc, olo, ohi);
        out[c * HW + gy * IMW + gx]       = -olo;
        out[c * HW + (gy + 1) * IMW + gx] = -ohi;
    }
}

extern "C" void kernel_launch(void* const* d_in, const int* in_sizes, int n_in,
                              void* d_out, int out_size) {
    const float* inp   = (const float*)d_in[0];
    const float* depth = (const float*)d_in[1];
    const float* alb   = (const float*)d_in[2];
    const float* nrm   = (const float*)d_in[3];
    float* out = (float*)d_out;

    dim3 grid(IMW / TILE_W, IMH / TILE_H);
    ls_kernel<<<grid, 256>>>(inp, depth, alb, nrm, out);
}

// round 3
// speedup vs baseline: 1.0015x; 1.0015x over previous
#include <cuda_runtime.h>

#define IMW 1024
#define IMH 1024
#define HW  (IMW * IMH)
#define TILE_W 16
#define TILE_H 32
#define HALO_W (TILE_W + 6)   // 22
#define HALO_H (TILE_H + 6)   // 38
#define SSTRIDE 24            // feature smem row stride (floats)
#define CH_STRIDE (HALO_H * SSTRIDE)          // 912 floats / channel
#define FEAT_WORDS (11 * CH_STRIDE)           // 10032
#define HS_COLSTRIDE 62                        // padded: conflict-free 64b phases
#define HS_ROWSTRIDE (TILE_W * HS_COLSTRIDE)   // 992
#define HS_WORDS (HALO_H * HS_ROWSTRIDE)       // 37696
#define SMEM_BYTES ((FEAT_WORDS + HS_WORDS) * 4)   // 190912
#define EPSR 1e-4f

typedef unsigned long long ull;

// ---- packed f32x2 helpers -------------------------------------------------
__device__ __forceinline__ ull pk2(float lo, float hi) {
    ull r;
    asm("mov.b64 %0, {%1, %2};" : "=l"(r) : "f"(lo), "f"(hi));
    return r;
}
__device__ __forceinline__ void ffma2(ull& d, ull a, ull b) {
    asm("fma.rn.f32x2 %0, %1, %2, %0;" : "+l"(d) : "l"(a), "l"(b));
}
__device__ __forceinline__ ull ffma2g(ull a, ull b, ull c) {
    ull r;
    asm("fma.rn.f32x2 %0, %1, %2, %3;" : "=l"(r) : "l"(a), "l"(b), "l"(c));
    return r;
}
__device__ __forceinline__ ull mul2(ull a, ull b) {
    ull r;
    asm("mul.rn.f32x2 %0, %1, %2;" : "=l"(r) : "l"(a), "l"(b));
    return r;
}
__device__ __forceinline__ ull add2(ull a, ull b) {
    ull r;
    asm("add.rn.f32x2 %0, %1, %2;" : "=l"(r) : "l"(a), "l"(b));
    return r;
}
__device__ __forceinline__ void upk2(ull v, float& lo, float& hi) {
    asm("mov.b64 {%0, %1}, %2;" : "=f"(lo), "=f"(hi) : "l"(v));
}
__device__ __forceinline__ float frcp(float x) {
    float r;
    asm("rcp.approx.f32 %0, %1;" : "=f"(r) : "f"(x));
    return r;
}
__host__ __device__ constexpr int IDX(int i, int j) {  // upper-tri 8x8, i<=j
    return i * 8 - i * (i - 1) / 2 + (j - i);
}

// load one tap: 11 channels, vertical row pair packed (rows r, r+1)
__device__ __forceinline__ void loadtap(ull v[11], const float* __restrict__ p) {
#pragma unroll
    for (int ch = 0; ch < 11; ++ch)
        v[ch] = pk2(p[ch * CH_STRIDE], p[ch * CH_STRIDE + SSTRIDE]);
}

// 60 packed moment accumulations: acc[0..35]=AtA upper tri, acc[36..59]=AtY
__device__ __forceinline__ void fma60(const ull v[11], ull acc[60]) {
    int k = 0;
#pragma unroll
    for (int i = 0; i < 8; ++i)
#pragma unroll
        for (int j = i; j < 8; ++j) { ffma2(acc[k], v[i], v[j]); ++k; }
#pragma unroll
    for (int i = 0; i < 8; ++i)
#pragma unroll
        for (int c = 0; c < 3; ++c) ffma2(acc[36 + i * 3 + c], v[i], v[8 + c]);
}

// load 15 float2 (30 moments) from hsum row
__device__ __forceinline__ void load15(ull d[15], const float* __restrict__ p) {
#pragma unroll
    for (int j = 0; j < 15; ++j) {
        float2 t = *(const float2*)(p + 2 * j);
        d[j] = pk2(t.x, t.y);
    }
}

__global__ __launch_bounds__(256)
void ls_kernel(const float* __restrict__ inp,
               const float* __restrict__ depth,
               const float* __restrict__ alb,
               const float* __restrict__ nrm,
               float* __restrict__ out)
{
    extern __shared__ float SM[];
    float* S  = SM;                 // features: 11 ch x (38 x 24)
    float* HS = SM + FEAT_WORDS;    // hsums: 38 rows x 16 cols x 62

    const int tid = threadIdx.x;
    const int bx = blockIdx.x, by = blockIdx.y;
    const int gx0 = bx * TILE_W - 3;
    const int gy0 = by * TILE_H - 3;

    // ---- phase 0: stage halo features (zeros outside image) ----
    for (int idx = tid; idx < HALO_H * HALO_W; idx += 256) {
        const int r = idx / HALO_W;
        const int c = idx - r * HALO_W;
        const int gy = gy0 + r;
        const int gx = gx0 + c;
        float v[11];
        if ((unsigned)gy < (unsigned)IMH && (unsigned)gx < (unsigned)IMW) {
            const int g = gy * IMW + gx;
            v[0] = 1.0f;
            v[1] = depth[g];
            v[2] = alb[g];  v[3] = alb[g + HW];  v[4] = alb[g + 2 * HW];
            v[5] = nrm[g];  v[6] = nrm[g + HW];  v[7] = nrm[g + 2 * HW];
            v[8] = inp[g];  v[9] = inp[g + HW];  v[10] = inp[g + 2 * HW];
        } else {
#pragma unroll
            for (int ch = 0; ch < 11; ++ch) v[ch] = 0.0f;
        }
#pragma unroll
        for (int ch = 0; ch < 11; ++ch)
            S[ch * CH_STRIDE + r * SSTRIDE + c] = v[ch];
    }
    __syncthreads();

    // ---- phase 1: horizontal 7-tap moment sums for all 38 halo rows ----
    // job = (row pair rp, output col c); 19*16 = 304 jobs
#pragma unroll 1
    for (int job = tid; job < 19 * TILE_W; job += 256) {
        const int rp = job >> 4;        // row pair: rows 2rp, 2rp+1
        const int c  = job & 15;        // output col (halo col = c..c+6)
        const float* base = &S[(2 * rp) * SSTRIDE + c];

        ull acc[60];
#pragma unroll
        for (int m = 0; m < 60; ++m) acc[m] = 0ULL;
#pragma unroll
        for (int dx = 0; dx < 7; ++dx) {
            ull v[11];
            loadtap(v, base + dx);
            fma60(v, acc);
        }
        float* hp0 = &HS[(2 * rp) * HS_ROWSTRIDE + c * HS_COLSTRIDE];
        float* hp1 = hp0 + HS_ROWSTRIDE;
#pragma unroll
        for (int m = 0; m < 60; m += 2) {
            float a0, b0, a1, b1;
            upk2(acc[m], a0, b0);
            upk2(acc[m + 1], a1, b1);
            *(float2*)(hp0 + m) = make_float2(a0, a1);  // row 2rp
            *(float2*)(hp1 + m) = make_float2(b0, b1);  // row 2rp+1
        }
    }
    __syncthreads();

    // ---- phase 2: vertical 7-tap sums for the two output pixels ----
    const int lx = tid & 15;
    const int ly0 = (tid >> 4) * 2;
    const float* hb = &HS[ly0 * HS_ROWSTRIDE + lx * HS_COLSTRIDE];

    ull atap[60];  // pixel-packed moments: [36 AtA tri, 24 AtY]
#pragma unroll
    for (int h = 0; h < 2; ++h) {
        const float* hp = hb + 30 * h;
        ull com[15], t[15], e0[15], e1[15];
        load15(com, hp + 1 * HS_ROWSTRIDE);
#pragma unroll
        for (int k = 2; k <= 6; ++k) {
            load15(t, hp + k * HS_ROWSTRIDE);
#pragma unroll
            for (int j = 0; j < 15; ++j) com[j] = add2(com[j], t[j]);
        }
        load15(t, hp);                       // row ly0 -> pixel 0 extra
#pragma unroll
        for (int j = 0; j < 15; ++j) e0[j] = add2(com[j], t[j]);
        load15(t, hp + 7 * HS_ROWSTRIDE);    // row ly0+7 -> pixel 1 extra
#pragma unroll
        for (int j = 0; j < 15; ++j) e1[j] = add2(com[j], t[j]);
        // transpose moment-packed -> pixel-packed
#pragma unroll
        for (int j = 0; j < 15; ++j) {
            float p0a, p0b, p1a, p1b;
            upk2(e0[j], p0a, p0b);
            upk2(e1[j], p1a, p1b);
            atap[30 * h + 2 * j]     = pk2(p0a, p1a);
            atap[30 * h + 2 * j + 1] = pk2(p0b, p1b);
        }
    }

    ull* ata = atap;
    ull* aty = atap + 36;

    // ---- packed symmetric solve (both pixels at once) ----
    const ull EPS2 = pk2(EPSR, EPSR);
#pragma unroll
    for (int i = 0; i < 8; ++i) ata[IDX(i, i)] = add2(ata[IDX(i, i)], EPS2);

    ull rhs[8];
    {
        const float* cp = &S[(ly0 + 3) * SSTRIDE + (lx + 3)];
#pragma unroll
        for (int i = 0; i < 8; ++i)
            rhs[i] = pk2(cp[i * CH_STRIDE], cp[i * CH_STRIDE + SSTRIDE]);
    }

#pragma unroll
    for (int k = 0; k < 8; ++k) {
        float dlo, dhi;
        upk2(ata[IDX(k, k)], dlo, dhi);
        const ull ninv = pk2(-frcp(dlo), -frcp(dhi));
#pragma unroll
        for (int i = k + 1; i < 8; ++i) {
            const ull li = mul2(ata[IDX(k, i)], ninv);   // -a_ki / d_k
            rhs[i] = ffma2g(li, rhs[k], rhs[i]);
#pragma unroll
            for (int j = i; j < 8; ++j)
                ata[IDX(i, j)] = ffma2g(li, ata[IDX(k, j)], ata[IDX(i, j)]);
        }
    }
    ull nx[8];
#pragma unroll
    for (int i = 7; i >= 0; --i) {
        ull s = rhs[i];
#pragma unroll
        for (int j = 7; j > i; --j)
            s = ffma2g(ata[IDX(i, j)], nx[j], s);
        float dlo, dhi;
        upk2(ata[IDX(i, i)], dlo, dhi);
        nx[i] = mul2(s, pk2(-frcp(dlo), -frcp(dhi)));
    }

    // out_c = x . AtY_c = -(nx . AtY_c)
    const int gy = by * TILE_H + ly0;
    const int gx = bx * TILE_W + lx;
#pragma unroll
    for (int c = 0; c < 3; ++c) {
        ull acc = 0ULL;
#pragma unroll
        for (int i = 0; i < 8; ++i)
            ffma2(acc, nx[i], aty[i * 3 + c]);
        float olo, ohi;
        upk2(acc, olo, ohi);
        out[c * HW + gy * IMW + gx]       = -olo;
        out[c * HW + (gy + 1) * IMW + gx] = -ohi;
    }
}

extern "C" void kernel_launch(void* const* d_in, const int* in_sizes, int n_in,
                              void* d_out, int out_size) {
    const float* inp   = (const float*)d_in[0];
    const float* depth = (const float*)d_in[1];
    const float* alb   = (const float*)d_in[2];
    const float* nrm   = (const float*)d_in[3];
    float* out = (float*)d_out;

    cudaFuncSetAttribute(ls_kernel, cudaFuncAttributeMaxDynamicSharedMemorySize,
                         SMEM_BYTES);
    dim3 grid(IMW / TILE_W, IMH / TILE_H);
    ls_kernel<<<grid, 256, SMEM_BYTES>>>(inp, depth, alb, nrm, out);
}

// round 4
// speedup vs baseline: 1.0234x; 1.0219x over previous
#include <cuda_runtime.h>

#define IMW 1024
#define IMH 1024
#define HW  (IMW * IMH)
#define TW 16
#define TH 16
#define HALO 22
#define RP 11                    // row pairs per column
#define FCH (HALO * RP)          // 242 ull per feature channel
#define F_ULL (11 * FCH)         // 2662 ull
#define HSK 16                   // HS: c-count (stride between k)
#define HSM (RP * HSK)           // 176 ull per moment
#define HS_ULL (60 * HSM)        // 10560 ull
#define SMEM_BYTES ((F_ULL + HS_ULL) * 8)   // 105,776 B
#define EPSR 1e-4f

typedef unsigned long long ull;

// ---- packed f32x2 helpers -------------------------------------------------
__device__ __forceinline__ ull pk2(float lo, float hi) {
    ull r;
    asm("mov.b64 %0, {%1, %2};" : "=l"(r) : "f"(lo), "f"(hi));
    return r;
}
__device__ __forceinline__ void ffma2(ull& d, ull a, ull b) {
    asm("fma.rn.f32x2 %0, %1, %2, %0;" : "+l"(d) : "l"(a), "l"(b));
}
__device__ __forceinline__ ull ffma2g(ull a, ull b, ull c) {
    ull r;
    asm("fma.rn.f32x2 %0, %1, %2, %3;" : "=l"(r) : "l"(a), "l"(b), "l"(c));
    return r;
}
__device__ __forceinline__ ull mul2(ull a, ull b) {
    ull r;
    asm("mul.rn.f32x2 %0, %1, %2;" : "=l"(r) : "l"(a), "l"(b));
    return r;
}
__device__ __forceinline__ ull add2(ull a, ull b) {
    ull r;
    asm("add.rn.f32x2 %0, %1, %2;" : "=l"(r) : "l"(a), "l"(b));
    return r;
}
__device__ __forceinline__ void upk2(ull v, float& lo, float& hi) {
    asm("mov.b64 {%0, %1}, %2;" : "=f"(lo), "=f"(hi) : "l"(v));
}
__device__ __forceinline__ float frcp(float x) {
    float r;
    asm("rcp.approx.f32 %0, %1;" : "=f"(r) : "f"(x));
    return r;
}
__host__ __device__ constexpr int IDX(int i, int j) {  // upper-tri 8x8, i<=j
    return i * 8 - i * (i - 1) / 2 + (j - i);
}

__global__ __launch_bounds__(128)
void ls_kernel(const float* __restrict__ inp,
               const float* __restrict__ depth,
               const float* __restrict__ alb,
               const float* __restrict__ nrm,
               float* __restrict__ out)
{
    extern __shared__ ull SMU[];
    ull* F  = SMU;            // F[ch][col][rowpair] : ull = (row2k, row2k+1)
    ull* HS = SMU + F_ULL;    // HS[m][k][c]
    float* Fw = (float*)F;

    const int tid = threadIdx.x;
    const int bx = blockIdx.x, by = blockIdx.y;
    const int gx0 = bx * TW - 3;
    const int gy0 = by * TH - 3;

    // ---- phase 0: stage halo features, transposed row-pair layout ----
    for (int idx = tid; idx < HALO * HALO; idx += 128) {
        const int r = idx / HALO;
        const int c = idx - r * HALO;
        const int gy = gy0 + r;
        const int gx = gx0 + c;
        float v[11];
        if ((unsigned)gy < (unsigned)IMH && (unsigned)gx < (unsigned)IMW) {
            const int g = gy * IMW + gx;
            v[0] = 1.0f;
            v[1] = depth[g];
            v[2] = alb[g];  v[3] = alb[g + HW];  v[4] = alb[g + 2 * HW];
            v[5] = nrm[g];  v[6] = nrm[g + HW];  v[7] = nrm[g + 2 * HW];
            v[8] = inp[g];  v[9] = inp[g + HW];  v[10] = inp[g + 2 * HW];
        } else {
#pragma unroll
            for (int ch = 0; ch < 11; ++ch) v[ch] = 0.0f;
        }
        const int w = (c * RP + (r >> 1)) * 2 + (r & 1);
#pragma unroll
        for (int ch = 0; ch < 11; ++ch)
            Fw[ch * (2 * FCH) + w] = v[ch];
    }
    __syncthreads();

    // ---- phase 1: horizontal 7-tap moment sums, 30 moments per thread ----
    // job: c = out col (16), t = job>>4 in 0..21 -> (h, rowpair)
#pragma unroll 1
    for (int job = tid; job < 22 * 16; job += 128) {
        const int c = job & 15;
        const int t = job >> 4;
        const int h = (t >= RP) ? 1 : 0;
        const int rp = h ? (t - RP) : t;
        const ull* fb = F + c * RP + rp;

        if (h == 0) {
            ull acc[30];
#pragma unroll
            for (int m = 0; m < 30; ++m) acc[m] = 0ULL;
#pragma unroll
            for (int dx = 0; dx < 7; ++dx) {
                ull v[8];
#pragma unroll
                for (int ch = 0; ch < 8; ++ch)
                    v[ch] = fb[ch * FCH + dx * RP];
                int k = 0;
#pragma unroll
                for (int i = 0; i < 5; ++i)
#pragma unroll
                    for (int j = i; j < 8; ++j) { ffma2(acc[k], v[i], v[j]); ++k; }
            }
            ull* hp = HS + rp * HSK + c;
#pragma unroll
            for (int m = 0; m < 30; ++m) hp[m * HSM] = acc[m];
        } else {
            ull acc[30];
#pragma unroll
            for (int m = 0; m < 30; ++m) acc[m] = 0ULL;
#pragma unroll
            for (int dx = 0; dx < 7; ++dx) {
                ull v[11];
#pragma unroll
                for (int ch = 0; ch < 11; ++ch)
                    v[ch] = fb[ch * FCH + dx * RP];
                int k = 0;
#pragma unroll
                for (int i = 5; i < 8; ++i)
#pragma unroll
                    for (int j = i; j < 8; ++j) { ffma2(acc[k], v[i], v[j]); ++k; }
#pragma unroll
                for (int i = 0; i < 8; ++i)
#pragma unroll
                    for (int cc = 0; cc < 3; ++cc) { ffma2(acc[k], v[i], v[8 + cc]); ++k; }
            }
            ull* hp = HS + 30 * HSM + rp * HSK + c;
#pragma unroll
            for (int m = 0; m < 30; ++m) hp[m * HSM] = acc[m];
        }
    }
    __syncthreads();

    // ---- phase 2: vertical sums, one moment at a time (no big temps) ----
    const int lx = tid & 15;
    const int ty = tid >> 4;              // 0..7; pixel rows 2ty, 2ty+1

    ull atap[60];                          // [36 AtA tri | 24 AtY], pixel-packed
    const ull* hb = HS + ty * HSK + lx;
#pragma unroll
    for (int m = 0; m < 60; ++m) {
        const ull P0 = hb[m * HSM];
        const ull P1 = hb[m * HSM + HSK];
        const ull P2 = hb[m * HSM + 2 * HSK];
        const ull P3 = hb[m * HSM + 3 * HSK];
        const ull T = add2(add2(P0, P1), add2(P2, P3));
        float tl, th2, p0l, p0h, p3l, p3h;
        upk2(T, tl, th2);
        upk2(P0, p0l, p0h);
        upk2(P3, p3l, p3h);
        const float tt = tl + th2;        // sum of rows 2ty .. 2ty+7
        atap[m] = pk2(tt - p3h, tt - p0l);  // (pixel y0, pixel y1)
    }

    ull* ata = atap;
    ull* aty = atap + 36;

    // ---- packed symmetric solve (both pixels at once) ----
    const ull EPS2 = pk2(EPSR, EPSR);
#pragma unroll
    for (int i = 0; i < 8; ++i) ata[IDX(i, i)] = add2(ata[IDX(i, i)], EPS2);

    ull rhs[8];
    {
        const int colb = (lx + 3) * RP;
#pragma unroll
        for (int ch = 0; ch < 8; ++ch) {
            const float f0 = Fw[(ch * FCH + colb + ty + 1) * 2 + 1];  // row 2ty+3
            const float f1 = Fw[(ch * FCH + colb + ty + 2) * 2 + 0];  // row 2ty+4
            rhs[ch] = pk2(f0, f1);
        }
    }

#pragma unroll
    for (int k = 0; k < 8; ++k) {
        float dlo, dhi;
        upk2(ata[IDX(k, k)], dlo, dhi);
        const ull ninv = pk2(-frcp(dlo), -frcp(dhi));
#pragma unroll
        for (int i = k + 1; i < 8; ++i) {
            const ull li = mul2(ata[IDX(k, i)], ninv);   // -a_ki / d_k
            rhs[i] = ffma2g(li, rhs[k], rhs[i]);
#pragma unroll
            for (int j = i; j < 8; ++j)
                ata[IDX(i, j)] = ffma2g(li, ata[IDX(k, j)], ata[IDX(i, j)]);
        }
    }
    ull nx[8];
#pragma unroll
    for (int i = 7; i >= 0; --i) {
        ull s = rhs[i];
#pragma unroll
        for (int j = 7; j > i; --j)
            s = ffma2g(ata[IDX(i, j)], nx[j], s);
        float dlo, dhi;
        upk2(ata[IDX(i, i)], dlo, dhi);
        nx[i] = mul2(s, pk2(-frcp(dlo), -frcp(dhi)));
    }

    // out_c = x . AtY_c = -(nx . AtY_c)
    const int gy = by * TH + 2 * ty;
    const int gx = bx * TW + lx;
#pragma unroll
    for (int c = 0; c < 3; ++c) {
        ull acc = 0ULL;
#pragma unroll
        for (int i = 0; i < 8; ++i)
            ffma2(acc, nx[i], aty[i * 3 + c]);
        float olo, ohi;
        upk2(acc, olo, ohi);
        out[c * HW + gy * IMW + gx]       = -olo;
        out[c * HW + (gy + 1) * IMW + gx] = -ohi;
    }
}

extern "C" void kernel_launch(void* const* d_in, const int* in_sizes, int n_in,
                              void* d_out, int out_size) {
    const float* inp   = (const float*)d_in[0];
    const float* depth = (const float*)d_in[1];
    const float* alb   = (const float*)d_in[2];
    const float* nrm   = (const float*)d_in[3];
    float* out = (float*)d_out;

    cudaFuncSetAttribute(ls_kernel, cudaFuncAttributeMaxDynamicSharedMemorySize,
                         SMEM_BYTES);
    dim3 grid(IMW / TW, IMH / TH);
    ls_kernel<<<grid, 128, SMEM_BYTES>>>(inp, depth, alb, nrm, out);
}

// round 5
// speedup vs baseline: 1.3238x; 1.2935x over previous
#include <cuda_runtime.h>

#define IMW 1024
#define IMH 1024
#define HW  (IMW * IMH)
#define TW 16
#define TH 32
#define HALO_W 22
#define HALO_H 38
#define EPAIRS 19                 // E[k] = rows (2k, 2k+1), k=0..18
#define OPAIRS 18                 // O[k] = rows (2k+1, 2k+2), k=0..17
#define CSTR 22                   // ull per pair-row (22 cols, no pad needed)
#define ECH (EPAIRS * CSTR)       // 418 ull per channel
#define OCH (OPAIRS * CSTR)       // 396 ull per channel
#define E_ULL (11 * ECH)          // 4598
#define O_ULL (11 * OCH)          // 4356
#define SMEM_BYTES ((E_ULL + O_ULL) * 8)   // 71,632 B
#define EPSR 1e-4f

typedef unsigned long long ull;

// ---- packed f32x2 helpers -------------------------------------------------
__device__ __forceinline__ ull pk2(float lo, float hi) {
    ull r;
    asm("mov.b64 %0, {%1, %2};" : "=l"(r) : "f"(lo), "f"(hi));
    return r;
}
__device__ __forceinline__ void ffma2(ull& d, ull a, ull b) {
    asm("fma.rn.f32x2 %0, %1, %2, %0;" : "+l"(d) : "l"(a), "l"(b));
}
__device__ __forceinline__ ull ffma2g(ull a, ull b, ull c) {
    ull r;
    asm("fma.rn.f32x2 %0, %1, %2, %3;" : "=l"(r) : "l"(a), "l"(b), "l"(c));
    return r;
}
__device__ __forceinline__ ull mul2(ull a, ull b) {
    ull r;
    asm("mul.rn.f32x2 %0, %1, %2;" : "=l"(r) : "l"(a), "l"(b));
    return r;
}
__device__ __forceinline__ ull add2(ull a, ull b) {
    ull r;
    asm("add.rn.f32x2 %0, %1, %2;" : "=l"(r) : "l"(a), "l"(b));
    return r;
}
__device__ __forceinline__ void upk2(ull v, float& lo, float& hi) {
    asm("mov.b64 {%0, %1}, %2;" : "=f"(lo), "=f"(hi) : "l"(v));
}
__device__ __forceinline__ float frcp(float x) {
    float r;
    asm("rcp.approx.f32 %0, %1;" : "=f"(r) : "f"(x));
    return r;
}
__host__ __device__ constexpr int IDX(int i, int j) {  // upper-tri 8x8, i<=j
    return i * 8 - i * (i - 1) / 2 + (j - i);
}

// one tap: 11 channels, each a single LDS.64 of a packed row pair
__device__ __forceinline__ void loadtapE(ull v[11], const ull* __restrict__ p) {
#pragma unroll
    for (int ch = 0; ch < 11; ++ch) v[ch] = p[ch * ECH];
}
__device__ __forceinline__ void loadtapO(ull v[11], const ull* __restrict__ p) {
#pragma unroll
    for (int ch = 0; ch < 11; ++ch) v[ch] = p[ch * OCH];
}

// 60 packed moment accumulations
__device__ __forceinline__ void fma60(const ull v[11], ull ata[36], ull aty[24]) {
    int k = 0;
#pragma unroll
    for (int i = 0; i < 8; ++i)
#pragma unroll
        for (int j = i; j < 8; ++j) { ffma2(ata[k], v[i], v[j]); ++k; }
#pragma unroll
    for (int i = 0; i < 8; ++i)
#pragma unroll
        for (int c = 0; c < 3; ++c) ffma2(aty[i * 3 + c], v[i], v[8 + c]);
}

__global__ __launch_bounds__(256)
void ls_kernel(const float* __restrict__ inp,
               const float* __restrict__ depth,
               const float* __restrict__ alb,
               const float* __restrict__ nrm,
               float* __restrict__ out)
{
    extern __shared__ ull SMU[];
    ull* E = SMU;             // E[ch][k][col] = (f[2k], f[2k+1])
    ull* O = SMU + E_ULL;     // O[ch][k][col] = (f[2k+1], f[2k+2])
    float* Ew = (float*)E;
    float* Ow = (float*)O;

    const int tid = threadIdx.x;
    const int bx = blockIdx.x, by = blockIdx.y;
    const int gx0 = bx * TW - 3;
    const int gy0 = by * TH - 3;

    // ---- stage halo features into BOTH parity-paired layouts ----
    for (int idx = tid; idx < HALO_H * HALO_W; idx += 256) {
        const int r = idx / HALO_W;          // local row 0..37
        const int c = idx - r * HALO_W;      // local col 0..21
        const int gy = gy0 + r;
        const int gx = gx0 + c;
        float v[11];
        if ((unsigned)gy < (unsigned)IMH && (unsigned)gx < (unsigned)IMW) {
            const int g = gy * IMW + gx;
            v[0] = 1.0f;
            v[1] = depth[g];
            v[2] = alb[g];  v[3] = alb[g + HW];  v[4] = alb[g + 2 * HW];
            v[5] = nrm[g];  v[6] = nrm[g + HW];  v[7] = nrm[g + 2 * HW];
            v[8] = inp[g];  v[9] = inp[g + HW];  v[10] = inp[g + 2 * HW];
        } else {
#pragma unroll
            for (int ch = 0; ch < 11; ++ch) v[ch] = 0.0f;
        }
        if (r & 1) {
            const int ke = r >> 1;               // E[ke] hi
            const int ko = r >> 1;               // O[ko] lo (rows 2ko+1 = r)
#pragma unroll
            for (int ch = 0; ch < 11; ++ch) {
                Ew[(ch * ECH + ke * CSTR + c) * 2 + 1] = v[ch];
                if (r < 37)
                    Ow[(ch * OCH + ko * CSTR + c) * 2 + 0] = v[ch];
            }
        } else {
            const int ke = r >> 1;               // E[ke] lo
            const int ko = (r >> 1) - 1;         // O[ko] hi (rows 2ko+2 = r)
#pragma unroll
            for (int ch = 0; ch < 11; ++ch) {
                Ew[(ch * ECH + ke * CSTR + c) * 2 + 0] = v[ch];
                if (r >= 2)
                    Ow[(ch * OCH + ko * CSTR + c) * 2 + 1] = v[ch];
            }
        }
    }
    __syncthreads();

    // ---- accumulation: two vertically adjacent pixels, packed f32x2 ----
    const int lx = tid & 15;
    const int ty = tid >> 4;
    const int ly0 = ty * 2;                  // local pixel rows ly0, ly0+1

    ull ata[36];
    ull aty[24];
#pragma unroll
    for (int i = 0; i < 36; ++i) ata[i] = 0ULL;
#pragma unroll
    for (int i = 0; i < 24; ++i) aty[i] = 0ULL;

    // window row L = ly0+dy; pair (L, L+1): dy even -> E[ly0/2 + dy/2],
    // dy odd -> O[ly0/2 + (dy-1)/2]
    const ull* eb = E + (ly0 >> 1) * CSTR + lx;
    const ull* ob = O + (ly0 >> 1) * CSTR + lx;

#pragma unroll 1
    for (int j = 0; j < 3; ++j) {            // dy = 2j (E) and 2j+1 (O)
#pragma unroll
        for (int dx = 0; dx < 7; ++dx) {
            ull v[11];
            loadtapE(v, eb + dx);
            fma60(v, ata, aty);
        }
#pragma unroll
        for (int dx = 0; dx < 7; ++dx) {
            ull v[11];
            loadtapO(v, ob + dx);
            fma60(v, ata, aty);
        }
        eb += CSTR;
        ob += CSTR;
    }
    // dy = 6 (E row)
#pragma unroll
    for (int dx = 0; dx < 7; ++dx) {
        ull v[11];
        loadtapE(v, eb + dx);
        fma60(v, ata, aty);
    }

    // ---- packed symmetric solve (both pixels at once) ----
    const ull EPS2 = pk2(EPSR, EPSR);
#pragma unroll
    for (int i = 0; i < 8; ++i) ata[IDX(i, i)] = add2(ata[IDX(i, i)], EPS2);

    // RHS = center features, rows (ly0+3, ly0+4) = O[ly0/2 + 1], col lx+3
    ull rhs[8];
    {
        const ull* cp = O + (ly0 >> 1 + 0) * CSTR + CSTR + lx + 3;
#pragma unroll
        for (int ch = 0; ch < 8; ++ch) rhs[ch] = cp[ch * OCH];
    }

#pragma unroll
    for (int k = 0; k < 8; ++k) {
        float dlo, dhi;
        upk2(ata[IDX(k, k)], dlo, dhi);
        const ull ninv = pk2(-frcp(dlo), -frcp(dhi));
#pragma unroll
        for (int i = k + 1; i < 8; ++i) {
            const ull li = mul2(ata[IDX(k, i)], ninv);   // -a_ki / d_k
            rhs[i] = ffma2g(li, rhs[k], rhs[i]);
#pragma unroll
            for (int j = i; j < 8; ++j)
                ata[IDX(i, j)] = ffma2g(li, ata[IDX(k, j)], ata[IDX(i, j)]);
        }
    }
    ull nx[8];
#pragma unroll
    for (int i = 7; i >= 0; --i) {
        ull s = rhs[i];
#pragma unroll
        for (int j = 7; j > i; --j)
            s = ffma2g(ata[IDX(i, j)], nx[j], s);
        float dlo, dhi;
        upk2(ata[IDX(i, i)], dlo, dhi);
        nx[i] = mul2(s, pk2(-frcp(dlo), -frcp(dhi)));
    }

    // out_c = x . AtY_c = -(nx . AtY_c)
    const int gy = by * TH + ly0;
    const int gx = bx * TW + lx;
#pragma unroll
    for (int c = 0; c < 3; ++c) {
        ull acc = 0ULL;
#pragma unroll
        for (int i = 0; i < 8; ++i)
            ffma2(acc, nx[i], aty[i * 3 + c]);
        float olo, ohi;
        upk2(acc, olo, ohi);
        out[c * HW + gy * IMW + gx]       = -olo;
        out[c * HW + (gy + 1) * IMW + gx] = -ohi;
    }
}

extern "C" void kernel_launch(void* const* d_in, const int* in_sizes, int n_in,
                              void* d_out, int out_size) {
    const float* inp   = (const float*)d_in[0];
    const float* depth = (const float*)d_in[1];
    const float* alb   = (const float*)d_in[2];
    const float* nrm   = (const float*)d_in[3];
    float* out = (float*)d_out;

    cudaFuncSetAttribute(ls_kernel, cudaFuncAttributeMaxDynamicSharedMemorySize,
                         SMEM_BYTES);
    dim3 grid(IMW / TW, IMH / TH);
    ls_kernel<<<grid, 256, SMEM_BYTES>>>(inp, depth, alb, nrm, out);
}